// round 13
// baseline (speedup 1.0000x reference)
#include <cuda_runtime.h>
#include <math.h>

#define BB 32
#define PP 8732
#define MM 16
#define CC 81
#define THRESH 0.5f
#define NBLK 16
#define CH ((PP + NBLK - 1) / NBLK)     // 546 priors per match chunk
#define MB (BB * NBLK)                  // 512 match blocks
#define ROWS_PER_BLK 16                 // 4 warps x 4 rows
#define LSEB ((BB * PP) / ROWS_PER_BLK) // 17464 lse blocks (exact)

typedef unsigned long long ull;

// Scratch (no allocation allowed -> __device__ globals)
__device__ ull   g_pfo_part[BB * MM * NBLK];  // per-object partial keys
__device__ ull   g_pbest[BB * PP];            // per-prior (iou<<32 | 15-obj)
__device__ float g_lse[BB * PP];              // per-prior logsumexp
__device__ int   g_npos[BB];
__device__ float g_locsum[BB];
__device__ float g_pos[BB];
__device__ float g_hard[BB];
__device__ int   g_done;

// ==== K1: match blocks (one IoU pass, both reductions) + lse blocks ====
// (round-10 configuration: no reg cap, box coords cached in registers)
__global__ void __launch_bounds__(128) k1_kernel(
        const float* __restrict__ logits,
        const float* __restrict__ boxes,
        const float* __restrict__ priors) {
    __shared__ float s_iou[CH][4];
    __shared__ unsigned char s_obj[CH][4];
    __shared__ float s_box[MM][4];
    __shared__ float s_area[MM];

    const int tid = threadIdx.x;
    const int lane = tid & 31, warp = tid >> 5;

    if (blockIdx.x >= MB) {
        // -------- lse path: 8-lane group per row, 4 rows/warp, no smem ----
        const int g = lane >> 3, k = lane & 7;
        const int r = ((blockIdx.x - MB) * 4 + warp) * 4 + g;
        const float* rp = logits + (size_t)r * CC + k;
        float s = 0.f;
#pragma unroll
        for (int i = 0; i < 10; i++) s += __expf(rp[i * 8]);
        if (k == 0) s += __expf(rp[80]);
        s += __shfl_xor_sync(0xffffffffu, s, 4);
        s += __shfl_xor_sync(0xffffffffu, s, 2);
        s += __shfl_xor_sync(0xffffffffu, s, 1);
        if (k == 0) g_lse[r] = __logf(s);
        return;
    }

    // -------- match path: 4 warps x 4 objects over a 546-prior chunk ----
    const int b = blockIdx.x >> 4, c = blockIdx.x & 15;

    if (tid == 0 && c == 0 && b == 0) g_done = 0;
    if (tid < MM) {
        float4 bx = ((const float4*)boxes)[b * MM + tid];
        s_box[tid][0] = bx.x; s_box[tid][1] = bx.y;
        s_box[tid][2] = bx.z; s_box[tid][3] = bx.w;
        s_area[tid] = (bx.z - bx.x) * (bx.w - bx.y);
    }
    __syncthreads();

    const int mb = warp * 4;   // this warp's 4 objects
    float ax[4], ay[4], az[4], aw[4], ar[4];
#pragma unroll
    for (int j = 0; j < 4; j++) {
        ax[j] = s_box[mb + j][0]; ay[j] = s_box[mb + j][1];
        az[j] = s_box[mb + j][2]; aw[j] = s_box[mb + j][3];
        ar[j] = s_area[mb + j];
    }

    const int p0 = c * CH;
    const int p1 = (p0 + CH < PP) ? p0 + CH : PP;

    float biou[4]; int bp[4];
#pragma unroll
    for (int j = 0; j < 4; j++) { biou[j] = -1.f; bp[j] = 0; }

    for (int p = p0 + lane; p < p1; p += 32) {   // ascending p per lane
        float4 pr = ((const float4*)priors)[p];
        float px0 = pr.x - pr.z * 0.5f, py0 = pr.y - pr.w * 0.5f;
        float px1 = pr.x + pr.z * 0.5f, py1 = pr.y + pr.w * 0.5f;
        float parea = pr.z * pr.w;

        float q[4];
#pragma unroll
        for (int j = 0; j < 4; j++) {
            float iw = fmaxf(fminf(az[j], px1) - fmaxf(ax[j], px0), 0.f);
            float ih = fmaxf(fminf(aw[j], py1) - fmaxf(ay[j], py0), 0.f);
            float inter = iw * ih;
            q[j] = inter / (ar[j] + parea - inter);
            if (q[j] > biou[j]) { biou[j] = q[j]; bp[j] = p; } // lowest p
        }
        // per-prior best of this warp's 4 objects (strict >: lowest j)
        float qb = q[0]; int jb = 0;
#pragma unroll
        for (int j = 1; j < 4; j++)
            if (q[j] > qb) { qb = q[j]; jb = j; }
        s_iou[p - p0][warp] = qb;
        s_obj[p - p0][warp] = (unsigned char)(mb + jb);
    }

    // per-object partial keys -> global
#pragma unroll
    for (int j = 0; j < 4; j++) {
        ull k = (biou[j] < 0.f) ? 0ull :
            ((((ull)__float_as_uint(biou[j])) << 32) |
             (ull)(~(unsigned)bp[j]));
#pragma unroll
        for (int o = 16; o > 0; o >>= 1) {
            ull t = __shfl_down_sync(0xffffffffu, k, o);
            if (t > k) k = t;
        }
        if (lane == 0) g_pfo_part[(b * MM + mb + j) * NBLK + c] = k;
    }
    __syncthreads();

    // combine per-prior results across warps (ascending w: lowest m on ties)
    const int np = p1 - p0;
    for (int p = tid; p < np; p += 128) {
        float qb = s_iou[p][0]; int obj = s_obj[p][0];
#pragma unroll
        for (int w = 1; w < 4; w++) {
            float qw = s_iou[p][w];
            if (qw > qb) { qb = qw; obj = s_obj[p][w]; }
        }
        g_pbest[b * PP + p0 + p] =
            (((ull)__float_as_uint(qb)) << 32) | (unsigned)(15 - obj);
    }
}

// ==== K2: fused finalize + topk + final combine (1 block/image, 1024 thr) ====
#define NV2 9                  // ceil(8732/1024)
__global__ void __launch_bounds__(1024) fin_topk_kernel(
        const float* __restrict__ logits,
        const float* __restrict__ locs,
        const float* __restrict__ boxes,
        const int*   __restrict__ labels,
        const float* __restrict__ priors,
        float* __restrict__ out) {
    const int b = blockIdx.x;
    const int tid = threadIdx.x;
    const int lane = tid & 31, warp = tid >> 5;

    __shared__ float s_box[MM][4];
    __shared__ int   s_lab[MM];
    __shared__ ull   s_part[MM * NBLK];   // 256
    __shared__ int   s_pfo[MM];
    __shared__ float s_wf[32], s_wg[32];
    __shared__ int   s_wi[32];
    __shared__ int   s_cnt[2][32];
    __shared__ int   s_K;

    if (tid < MM * NBLK) s_part[tid] = g_pfo_part[b * (MM * NBLK) + tid];
    if (tid < MM) {
        float4 bx = ((const float4*)boxes)[b * MM + tid];
        s_box[tid][0] = bx.x; s_box[tid][1] = bx.y;
        s_box[tid][2] = bx.z; s_box[tid][3] = bx.w;
        s_lab[tid] = labels[b * MM + tid];
    }
    __syncthreads();
    if (tid < MM) {
        ull k = s_part[tid * NBLK];
#pragma unroll
        for (int i = 1; i < NBLK; i++)
            if (s_part[tid * NBLK + i] > k) k = s_part[tid * NBLK + i];
        s_pfo[tid] = (int)(~(unsigned)(k & 0xffffffffull));
    }
    __syncthreads();

    // ---- finalize: compute negloss in registers, pos/loc/npos reductions ----
    float v[NV2];
    float pos = 0.f, locsum = 0.f;
    int   posc = 0;
#pragma unroll
    for (int i = 0; i < NV2; i++) {
        const int p = i * 1024 + tid;
        v[i] = -1.f;                         // pad: never counted (thr > 0)
        if (p < PP) {
            ull key = g_pbest[b * PP + p];
            float iou = __uint_as_float((unsigned)(key >> 32));
            int   obj = 15 - (int)(key & 0xffffffffull);
#pragma unroll
            for (int m = 0; m < MM; m++)     // forced: ascending m, last wins
                if (s_pfo[m] == p) { obj = m; iou = 1.0f; }

            const int lab = (iou < THRESH) ? 0 : s_lab[obj];
            float loss = g_lse[b * PP + p]
                       - logits[((size_t)b * PP + p) * CC + lab];
            if (!isfinite(loss)) loss = 0.f;

            if (lab != 0) {
                pos += loss; posc++;
                v[i] = 0.f;                  // positives excluded from negatives
                float4 pr = ((const float4*)priors)[p];
                float bx0 = s_box[obj][0], by0 = s_box[obj][1];
                float bx1 = s_box[obj][2], by1 = s_box[obj][3];
                float g0 = ((bx0 + bx1) * 0.5f - pr.x) * 10.f / pr.z;
                float g1 = ((by0 + by1) * 0.5f - pr.y) * 10.f / pr.w;
                float g2 = logf((bx1 - bx0) / pr.z) * 5.f;
                float g3 = logf((by1 - by0) / pr.w) * 5.f;
                float4 pl = ((const float4*)locs)[b * PP + p];
                locsum += fabsf(pl.x - g0) + fabsf(pl.y - g1)
                        + fabsf(pl.z - g2) + fabsf(pl.w - g3);
            } else {
                v[i] = loss;
            }
        }
    }

    for (int o = 16; o > 0; o >>= 1) {
        pos    += __shfl_xor_sync(0xffffffffu, pos, o);
        locsum += __shfl_xor_sync(0xffffffffu, locsum, o);
        posc   += __shfl_xor_sync(0xffffffffu, posc, o);
    }
    if (lane == 0) { s_wf[warp] = pos; s_wg[warp] = locsum; s_wi[warp] = posc; }
    __syncthreads();
    if (tid == 0) {
        float tp = 0.f, tl = 0.f; int tc = 0;
#pragma unroll
        for (int w = 0; w < 32; w++) { tp += s_wf[w]; tl += s_wg[w]; tc += s_wi[w]; }
        g_pos[b] = tp; g_locsum[b] = tl; g_npos[b] = tc;
        int K = tc * 3; if (K > PP) K = PP;
        s_K = K;
    }
    __syncthreads();
    const int K = s_K;

    // ---- topk: exact top-K sum via binary search on float bits ----
    float hard = 0.f;
    if (K > 0) {
        unsigned lo = 0u, hi = 0x7f7fffffu;
        int it = 0;
        while (lo < hi) {
            const unsigned mid = lo + ((hi - lo + 1u) >> 1);
            const float t = __uint_as_float(mid);
            int c = 0;
#pragma unroll
            for (int i = 0; i < NV2; i++) c += (v[i] >= t) ? 1 : 0;
            c = __reduce_add_sync(0xffffffffu, c);
            const int par = it & 1;
            if (lane == 0) s_cnt[par][warp] = c;
            __syncthreads();                  // single barrier per iteration
            int tot = 0;
#pragma unroll
            for (int w = 0; w < 32; w++) tot += s_cnt[par][w];
            if (tot == K) { lo = mid; break; } // exact: top-K == {x >= mid}
            if (tot >= K) lo = mid; else hi = mid - 1u;
            it++;
        }
        const float thr = __uint_as_float(lo);

        int cgt = 0; float sgt = 0.f;
#pragma unroll
        for (int i = 0; i < NV2; i++) {
            float x = v[i];
            if (x > thr) { cgt++; sgt += x; }
        }
        cgt = __reduce_add_sync(0xffffffffu, cgt);
        for (int o = 16; o > 0; o >>= 1)
            sgt += __shfl_xor_sync(0xffffffffu, sgt, o);
        if (lane == 0) { s_wi[warp] = cgt; s_wf[warp] = sgt; }
        __syncthreads();
        if (tid == 0) {
            int tc = 0; float ts = 0.f;
#pragma unroll
            for (int w = 0; w < 32; w++) { tc += s_wi[w]; ts += s_wf[w]; }
            hard = ts + (float)(K - tc) * thr;
        }
    }
    if (tid == 0) g_hard[b] = hard;

    // ---- final combine: last block writes the scalar result ----
    __syncthreads();
    if (tid == 0) {
        __threadfence();
        int prev = atomicAdd(&g_done, 1);
        if (prev == BB - 1) {
            float n = 0.f, l = 0.f, cp = 0.f, hn = 0.f;
#pragma unroll
            for (int i = 0; i < BB; i++) {
                n += (float)g_npos[i]; l += g_locsum[i];
                cp += g_pos[i]; hn += g_hard[i];
            }
            out[0] = (cp + hn) / n + l / (4.f * n);
        }
    }
}

extern "C" void kernel_launch(void* const* d_in, const int* in_sizes, int n_in,
                              void* d_out, int out_size) {
    const float* locs   = (const float*)d_in[0];
    const float* logits = (const float*)d_in[1];
    const float* boxes  = (const float*)d_in[2];
    const int*   labels = (const int*)d_in[3];
    const float* priors = (const float*)d_in[4];
    float* out = (float*)d_out;

    k1_kernel<<<MB + LSEB, 128>>>(logits, boxes, priors);
    fin_topk_kernel<<<BB, 1024>>>(logits, locs, boxes, labels, priors, out);
}

// round 14
// speedup vs baseline: 1.1852x; 1.1852x over previous
#include <cuda_runtime.h>
#include <math.h>

#define BB 32
#define PP 8732
#define MM 16
#define CC 81
#define THRESH 0.5f
#define NBLK 16
#define CH ((PP + NBLK - 1) / NBLK)     // 546 priors per match chunk
#define MB (BB * NBLK)                  // 512 match blocks
#define LSEB ((BB * PP) / 32)           // 8732 lse blocks (32 rows each, exact)
#define NB2 8
#define CH2 ((PP + NB2 - 1) / NB2)      // 1092 priors per finalize chunk

typedef unsigned long long ull;

// Scratch (no allocation allowed -> __device__ globals)
__device__ ull   g_pfo_part[BB * MM * NBLK];  // per-object partial keys
__device__ ull   g_pbest[BB * PP];            // per-prior (iou<<32 | 15-obj)
__device__ float g_lse[BB * PP];              // per-prior logsumexp
__device__ float g_negloss[BB * PP];
__device__ int   g_npos[BB];
__device__ float g_locsum[BB];
__device__ float g_acc2[2];    // 0: pos_conf_sum, 1: hard_neg_sum
__device__ int   g_done;

// ==== K1: match blocks (2 obj/warp, 256 thr) + lse blocks (32 rows, 256 thr) ====
__global__ void __launch_bounds__(256) k1_kernel(
        const float* __restrict__ logits,
        const float* __restrict__ boxes,
        const float* __restrict__ priors) {
    __shared__ float s_iou[CH][8];          // 17.5KB (match blocks only)
    __shared__ unsigned char s_obj[CH][8];  // 4.4KB
    __shared__ float s_box[MM][4];
    __shared__ float s_area[MM];

    const int tid = threadIdx.x;
    const int lane = tid & 31, warp = tid >> 5;

    if (blockIdx.x >= MB) {
        // -------- lse path: 8-lane group per row, 4 rows/warp, 8 warps ----
        const int g = lane >> 3, k = lane & 7;
        const int r = ((blockIdx.x - MB) * 8 + warp) * 4 + g;
        const float* rp = logits + (size_t)r * CC + k;
        float s = 0.f;
#pragma unroll
        for (int i = 0; i < 10; i++) s += __expf(rp[i * 8]);
        if (k == 0) s += __expf(rp[80]);
        s += __shfl_xor_sync(0xffffffffu, s, 4);
        s += __shfl_xor_sync(0xffffffffu, s, 2);
        s += __shfl_xor_sync(0xffffffffu, s, 1);
        if (k == 0) g_lse[r] = __logf(s);
        return;
    }

    // -------- match path: 8 warps x 2 objects over a 546-prior chunk ----
    const int b = blockIdx.x >> 4, c = blockIdx.x & 15;

    if (tid == 0 && c == 0) {            // accumulator init
        g_locsum[b] = 0.f; g_npos[b] = 0;
        if (b == 0) { g_acc2[0] = 0.f; g_acc2[1] = 0.f; g_done = 0; }
    }
    if (tid < MM) {
        float4 bx = ((const float4*)boxes)[b * MM + tid];
        s_box[tid][0] = bx.x; s_box[tid][1] = bx.y;
        s_box[tid][2] = bx.z; s_box[tid][3] = bx.w;
        s_area[tid] = (bx.z - bx.x) * (bx.w - bx.y);
    }
    __syncthreads();

    const int mb = warp * 2;   // this warp's 2 objects
    float ax[2], ay[2], az[2], aw[2], ar[2];
#pragma unroll
    for (int j = 0; j < 2; j++) {
        ax[j] = s_box[mb + j][0]; ay[j] = s_box[mb + j][1];
        az[j] = s_box[mb + j][2]; aw[j] = s_box[mb + j][3];
        ar[j] = s_area[mb + j];
    }

    const int p0 = c * CH;
    const int p1 = (p0 + CH < PP) ? p0 + CH : PP;

    float biou[2]; int bp[2];
#pragma unroll
    for (int j = 0; j < 2; j++) { biou[j] = -1.f; bp[j] = 0; }

    for (int p = p0 + lane; p < p1; p += 32) {   // ascending p per lane
        float4 pr = ((const float4*)priors)[p];
        float px0 = pr.x - pr.z * 0.5f, py0 = pr.y - pr.w * 0.5f;
        float px1 = pr.x + pr.z * 0.5f, py1 = pr.y + pr.w * 0.5f;
        float parea = pr.z * pr.w;

        float q[2];
#pragma unroll
        for (int j = 0; j < 2; j++) {
            float iw = fmaxf(fminf(az[j], px1) - fmaxf(ax[j], px0), 0.f);
            float ih = fmaxf(fminf(aw[j], py1) - fmaxf(ay[j], py0), 0.f);
            float inter = iw * ih;
            q[j] = inter / (ar[j] + parea - inter);
            if (q[j] > biou[j]) { biou[j] = q[j]; bp[j] = p; } // lowest p
        }
        // per-prior best of this warp's 2 objects (strict >: lowest j)
        float qb = q[0]; int jb = 0;
        if (q[1] > qb) { qb = q[1]; jb = 1; }
        s_iou[p - p0][warp] = qb;
        s_obj[p - p0][warp] = (unsigned char)(mb + jb);
    }

    // per-object partial keys -> global
#pragma unroll
    for (int j = 0; j < 2; j++) {
        ull k = (biou[j] < 0.f) ? 0ull :
            ((((ull)__float_as_uint(biou[j])) << 32) |
             (ull)(~(unsigned)bp[j]));
#pragma unroll
        for (int o = 16; o > 0; o >>= 1) {
            ull t = __shfl_down_sync(0xffffffffu, k, o);
            if (t > k) k = t;
        }
        if (lane == 0) g_pfo_part[(b * MM + mb + j) * NBLK + c] = k;
    }
    __syncthreads();

    // combine per-prior results across warps (ascending w: lowest m on ties)
    const int np = p1 - p0;
    for (int p = tid; p < np; p += 256) {
        float qb = s_iou[p][0]; int obj = s_obj[p][0];
#pragma unroll
        for (int w = 1; w < 8; w++) {
            float qw = s_iou[p][w];
            if (qw > qb) { qb = qw; obj = s_obj[p][w]; }
        }
        g_pbest[b * PP + p0 + p] =
            (((ull)__float_as_uint(qb)) << 32) | (unsigned)(15 - obj);
    }
}

// ==== K2: finalize per prior (no IoU recompute) ====
__global__ void __launch_bounds__(256) k2_kernel(
        const float* __restrict__ logits,
        const float* __restrict__ locs,
        const float* __restrict__ boxes,
        const int*   __restrict__ labels,
        const float* __restrict__ priors) {
    const int b = blockIdx.x >> 3, c = blockIdx.x & 7;
    const int tid = threadIdx.x;
    const int lane = tid & 31, warp = tid >> 5;

    __shared__ float s_box[MM][4];
    __shared__ int   s_lab[MM];
    __shared__ ull   s_part[MM * NBLK];   // 256
    __shared__ int   s_pfo[MM];
    __shared__ float s_wpos[8], s_wloc[8];
    __shared__ int   s_wcnt[8];

    s_part[tid] = g_pfo_part[b * (MM * NBLK) + tid];
    if (tid < MM) {
        float4 bx = ((const float4*)boxes)[b * MM + tid];
        s_box[tid][0] = bx.x; s_box[tid][1] = bx.y;
        s_box[tid][2] = bx.z; s_box[tid][3] = bx.w;
        s_lab[tid] = labels[b * MM + tid];
    }
    __syncthreads();
    if (tid < MM) {
        ull k = s_part[tid * NBLK];
#pragma unroll
        for (int i = 1; i < NBLK; i++)
            if (s_part[tid * NBLK + i] > k) k = s_part[tid * NBLK + i];
        s_pfo[tid] = (int)(~(unsigned)(k & 0xffffffffull));
    }
    __syncthreads();

    const int p0 = c * CH2;
    const int p1 = (p0 + CH2 < PP) ? p0 + CH2 : PP;

    float pos = 0.f, locsum = 0.f;
    int   posc = 0;
    for (int p = p0 + tid; p < p1; p += 256) {
        ull key = g_pbest[b * PP + p];
        float iou = __uint_as_float((unsigned)(key >> 32));
        int   obj = 15 - (int)(key & 0xffffffffull);
#pragma unroll
        for (int m = 0; m < MM; m++)         // forced: ascending m, last wins
            if (s_pfo[m] == p) { obj = m; iou = 1.0f; }

        const int lab = (iou < THRESH) ? 0 : s_lab[obj];
        float loss = g_lse[b * PP + p] - logits[((size_t)b * PP + p) * CC + lab];
        if (!isfinite(loss)) loss = 0.f;

        if (lab != 0) {
            pos += loss; posc++;
            g_negloss[b * PP + p] = 0.f;
            float4 pr = ((const float4*)priors)[p];
            float bx0 = s_box[obj][0], by0 = s_box[obj][1];
            float bx1 = s_box[obj][2], by1 = s_box[obj][3];
            float g0 = ((bx0 + bx1) * 0.5f - pr.x) * 10.f / pr.z;
            float g1 = ((by0 + by1) * 0.5f - pr.y) * 10.f / pr.w;
            float g2 = logf((bx1 - bx0) / pr.z) * 5.f;
            float g3 = logf((by1 - by0) / pr.w) * 5.f;
            float4 pl = ((const float4*)locs)[b * PP + p];
            locsum += fabsf(pl.x - g0) + fabsf(pl.y - g1)
                    + fabsf(pl.z - g2) + fabsf(pl.w - g3);
        } else {
            g_negloss[b * PP + p] = loss;
        }
    }

    for (int o = 16; o > 0; o >>= 1) {
        pos    += __shfl_xor_sync(0xffffffffu, pos, o);
        locsum += __shfl_xor_sync(0xffffffffu, locsum, o);
        posc   += __shfl_xor_sync(0xffffffffu, posc, o);
    }
    if (lane == 0) { s_wpos[warp] = pos; s_wloc[warp] = locsum; s_wcnt[warp] = posc; }
    __syncthreads();
    if (tid == 0) {
        float tp = 0.f, tl = 0.f; int tc = 0;
#pragma unroll
        for (int w = 0; w < 8; w++) { tp += s_wpos[w]; tl += s_wloc[w]; tc += s_wcnt[w]; }
        if (tp != 0.f) atomicAdd(&g_acc2[0], tp);
        if (tl != 0.f) atomicAdd(&g_locsum[b], tl);
        if (tc != 0)   atomicAdd(&g_npos[b], tc);
    }
}

// ==== K3: topk, 512 threads, float4 loads, exact binary search ====
#define NQ 5   // ceil(2183 float4 / 512)
__global__ void __launch_bounds__(512) topk_kernel(float* __restrict__ out) {
    const int b = blockIdx.x, tid = threadIdx.x;
    const int lane = tid & 31, warp = tid >> 5;
    __shared__ int   s_cnt[2][16];
    __shared__ int   s_c2[16];
    __shared__ float s_sum[16];

    float4 v[NQ];
    const float4* src = (const float4*)(g_negloss + b * PP);   // PP%4==0
#pragma unroll
    for (int i = 0; i < NQ; i++) {
        const int idx = i * 512 + tid;
        v[i] = (idx < PP / 4) ? src[idx]
             : make_float4(-1.f, -1.f, -1.f, -1.f);   // pad: never counted
    }

    int K = g_npos[b] * 3;
    if (K > PP) K = PP;

    if (K > 0) {
        unsigned lo = 0u, hi = 0x7f7fffffu;
        int it = 0;
        while (lo < hi) {
            const unsigned mid = lo + ((hi - lo + 1u) >> 1);
            const float t = __uint_as_float(mid);
            int c = 0;
#pragma unroll
            for (int i = 0; i < NQ; i++) {
                c += (v[i].x >= t) ? 1 : 0;
                c += (v[i].y >= t) ? 1 : 0;
                c += (v[i].z >= t) ? 1 : 0;
                c += (v[i].w >= t) ? 1 : 0;
            }
            c = __reduce_add_sync(0xffffffffu, c);
            const int par = it & 1;
            if (lane == 0) s_cnt[par][warp] = c;
            __syncthreads();                  // single barrier per iteration
            int tot = 0;
#pragma unroll
            for (int w = 0; w < 16; w++) tot += s_cnt[par][w];
            if (tot == K) { lo = mid; break; } // exact: top-K == {x >= mid}
            if (tot >= K) lo = mid; else hi = mid - 1u;
            it++;
        }
        const float thr = __uint_as_float(lo);

        int cgt = 0; float sgt = 0.f;
#pragma unroll
        for (int i = 0; i < NQ; i++) {
            if (v[i].x > thr) { cgt++; sgt += v[i].x; }
            if (v[i].y > thr) { cgt++; sgt += v[i].y; }
            if (v[i].z > thr) { cgt++; sgt += v[i].z; }
            if (v[i].w > thr) { cgt++; sgt += v[i].w; }
        }
        cgt = __reduce_add_sync(0xffffffffu, cgt);
        for (int o = 16; o > 0; o >>= 1)
            sgt += __shfl_xor_sync(0xffffffffu, sgt, o);
        if (lane == 0) { s_c2[warp] = cgt; s_sum[warp] = sgt; }
        __syncthreads();
        if (tid == 0) {
            int tc = 0; float ts = 0.f;
#pragma unroll
            for (int i = 0; i < 16; i++) { tc += s_c2[i]; ts += s_sum[i]; }
            atomicAdd(&g_acc2[1], ts + (float)(K - tc) * thr);
        }
    }

    // fused final combine: last block to finish writes the scalar result
    __syncthreads();
    if (tid == 0) {
        __threadfence();
        int prev = atomicAdd(&g_done, 1);
        if (prev == BB - 1) {
            float n = 0.f, l = 0.f;
#pragma unroll
            for (int i = 0; i < BB; i++) { n += (float)g_npos[i]; l += g_locsum[i]; }
            out[0] = (g_acc2[0] + g_acc2[1]) / n + l / (4.f * n);
        }
    }
}

extern "C" void kernel_launch(void* const* d_in, const int* in_sizes, int n_in,
                              void* d_out, int out_size) {
    const float* locs   = (const float*)d_in[0];
    const float* logits = (const float*)d_in[1];
    const float* boxes  = (const float*)d_in[2];
    const int*   labels = (const int*)d_in[3];
    const float* priors = (const float*)d_in[4];
    float* out = (float*)d_out;

    k1_kernel<<<MB + LSEB, 256>>>(logits, boxes, priors);
    k2_kernel<<<BB * NB2, 256>>>(logits, locs, boxes, labels, priors);
    topk_kernel<<<BB, 512>>>(out);
}